// round 2
// baseline (speedup 1.0000x reference)
#include <cuda_runtime.h>
#include <math.h>
#include <stdint.h>

// ---------------- constants ----------------
#define DIMC   1024
#define TEMBC  512
#define NTOK   3456     // NF*S = 24*144
#define TENC   128      // T
#define WQN    5        // number of windows
#define LWIN   1280     // T + CL*S
#define LVV    1152     // CL*S
#define SROW   576      // STRIDE*S
#define MQ     6400     // WQN*LWIN
#define MFF    3584     // TENC + NTOK
#define HEADS_ 16
#define HD_    64

// ---------------- device scratch ----------------
__device__ float g_emb1[6144];
__device__ float g_emb2[6144];
__device__ float g_x  [(size_t)MQ * DIMC];
__device__ float g_q  [(size_t)MQ * DIMC];
__device__ float g_k  [(size_t)MQ * DIMC];
__device__ float g_v  [(size_t)MQ * DIMC];
__device__ float g_ao [(size_t)MQ * DIMC];
__device__ float g_o2 [(size_t)MQ * DIMC];
__device__ float g_ffin [(size_t)MFF * DIMC];
__device__ float g_h1   [(size_t)MFF * 4096];
__device__ float g_ffout[(size_t)MFF * DIMC];

__constant__ float c_pyr[8] = {1.f,2.f,3.f,4.f,4.f,3.f,2.f,1.f};

// ---------------- helpers ----------------
__device__ __forceinline__ void block_reduce_2(float &s, float &s2) {
    __shared__ float ra[8], rb[8];
#pragma unroll
    for (int m = 16; m > 0; m >>= 1) {
        s  += __shfl_xor_sync(0xffffffffu, s,  m);
        s2 += __shfl_xor_sync(0xffffffffu, s2, m);
    }
    int wid = threadIdx.x >> 5;
    if ((threadIdx.x & 31) == 0) { ra[wid] = s; rb[wid] = s2; }
    __syncthreads();
    s  = ra[0]+ra[1]+ra[2]+ra[3]+ra[4]+ra[5]+ra[6]+ra[7];
    s2 = rb[0]+rb[1]+rb[2]+rb[3]+rb[4]+rb[5]+rb[6]+rb[7];
    __syncthreads();
}

__device__ __forceinline__ float gelu_tanh(float x) {
    float x3 = x * x * x;
    return 0.5f * x * (1.f + tanhf(0.79788456080286535588f * (x + 0.044715f * x3)));
}

// ---------------- emb = silu(temb) @ W + b (both emb1, emb2) ----------------
__global__ __launch_bounds__(256) void emb_kernel(
    const float* __restrict__ temb,
    const float* __restrict__ w1, const float* __restrict__ b1,
    const float* __restrict__ w2, const float* __restrict__ b2)
{
    __shared__ float st[TEMBC];
    int tid = threadIdx.x;
    for (int i = tid; i < TEMBC; i += 256) {
        float t = temb[i];
        st[i] = t / (1.f + expf(-t));
    }
    __syncthreads();
    int j = blockIdx.x * 256 + tid;  // 0..12287
    const float* w; const float* bb; float* out; int col;
    if (j < 6144) { w = w1; bb = b1; out = g_emb1; col = j; }
    else          { w = w2; bb = b2; out = g_emb2; col = j - 6144; }
    float acc = 0.f;
#pragma unroll 8
    for (int kk = 0; kk < TEMBC; kk++)
        acc += st[kk] * w[(size_t)kk * 6144 + col];
    out[col] = acc + bb[col];
}

// ---------------- build x = [mod-LN(enc); mod-LN(chunks)] ----------------
__global__ __launch_bounds__(256) void build_x_kernel(
    const float* __restrict__ hs, const float* __restrict__ enc,
    const float* __restrict__ g, const float* __restrict__ b)
{
    int row = blockIdx.x;               // 0..MQ-1
    int w = row / LWIN, l = row % LWIN;
    const float* src; int sc_off, sh_off;
    if (l < TENC) { src = enc + (size_t)l * DIMC; sc_off = 4096; sh_off = 3072; }
    else {
        int gidx = w * SROW + (l - TENC);
        src = hs + (size_t)gidx * DIMC; sc_off = 1024; sh_off = 0;
    }
    int tid = threadIdx.x;
    float x[4]; float s = 0.f, s2 = 0.f;
#pragma unroll
    for (int i = 0; i < 4; i++) {
        x[i] = src[tid + i * 256];
        s += x[i]; s2 += x[i] * x[i];
    }
    block_reduce_2(s, s2);
    float mean = s * (1.f / DIMC);
    float var  = s2 * (1.f / DIMC) - mean * mean;
    float inv  = rsqrtf(var + 1e-5f);
    float* dst = g_x + (size_t)row * DIMC;
#pragma unroll
    for (int i = 0; i < 4; i++) {
        int d = tid + i * 256;
        float v = (x[i] - mean) * inv * g[d] + b[d];
        dst[d] = v * (1.f + g_emb1[sc_off + d]) + g_emb1[sh_off + d];
    }
}

// ---------------- generic SGEMM: C = A(MxK) * B(KxN) [+bias][gelu] ----------------
// M % 128 == 0, N % 128 == 0, K % 16 == 0 (holds for all uses)
__global__ __launch_bounds__(256) void gemm_kernel(
    const float* __restrict__ A, const float* __restrict__ B,
    const float* __restrict__ bias, float* __restrict__ C,
    int M, int N, int K, int act)
{
    __shared__ float As[16][132];   // [BK][BM+4], transposed
    __shared__ float Bs[16][128];
    int bm = blockIdx.y, bn = blockIdx.x;
    int tid = threadIdx.x;
    int r0 = (tid >> 4) * 8, c0 = (tid & 15) * 8;
    float acc[8][8];
#pragma unroll
    for (int i = 0; i < 8; i++)
#pragma unroll
        for (int j = 0; j < 8; j++) acc[i][j] = 0.f;

    const float* Ab = A + (size_t)bm * 128 * K;
    const float* Bb = B + (size_t)bn * 128;

    for (int k0 = 0; k0 < K; k0 += 16) {
#pragma unroll
        for (int i = 0; i < 2; i++) {
            int f = tid + i * 256;           // 0..511
            int r = f >> 2; int kq = (f & 3) * 4;
            float4 av = *(const float4*)(Ab + (size_t)r * K + k0 + kq);
            As[kq + 0][r] = av.x; As[kq + 1][r] = av.y;
            As[kq + 2][r] = av.z; As[kq + 3][r] = av.w;
        }
#pragma unroll
        for (int i = 0; i < 2; i++) {
            int f = tid + i * 256;
            int kk = f >> 5; int cq = (f & 31) * 4;
            *(float4*)(&Bs[kk][cq]) = *(const float4*)(Bb + (size_t)(k0 + kk) * N + cq);
        }
        __syncthreads();
#pragma unroll
        for (int kk = 0; kk < 16; kk++) {
            float a[8], b[8];
            *(float4*)(a)     = *(const float4*)(&As[kk][r0]);
            *(float4*)(a + 4) = *(const float4*)(&As[kk][r0 + 4]);
            *(float4*)(b)     = *(const float4*)(&Bs[kk][c0]);
            *(float4*)(b + 4) = *(const float4*)(&Bs[kk][c0 + 4]);
#pragma unroll
            for (int i = 0; i < 8; i++)
#pragma unroll
                for (int j = 0; j < 8; j++)
                    acc[i][j] += a[i] * b[j];
        }
        __syncthreads();
    }

#pragma unroll
    for (int i = 0; i < 8; i++) {
        size_t row = (size_t)bm * 128 + r0 + i;
        float* Cp = C + row * N + bn * 128 + c0;
        float out[8];
#pragma unroll
        for (int j = 0; j < 8; j++) {
            float v = acc[i][j];
            if (bias) v += bias[bn * 128 + c0 + j];
            if (act)  v = gelu_tanh(v);
            out[j] = v;
        }
        *(float4*)(Cp)     = *(const float4*)(out);
        *(float4*)(Cp + 4) = *(const float4*)(out + 4);
    }
}

// ---------------- per-head LN on q/k (eps 1e-6) ----------------
__global__ __launch_bounds__(256) void qkln_kernel(
    float* __restrict__ buf, const float* __restrict__ g, const float* __restrict__ b)
{
    int seg  = blockIdx.x * 8 + (threadIdx.x >> 5);  // 0..MQ*16-1
    int lane = threadIdx.x & 31;
    float* p = buf + (size_t)(seg >> 4) * DIMC + (seg & 15) * HD_;
    float x0 = p[lane], x1 = p[lane + 32];
    float s = x0 + x1, s2 = x0 * x0 + x1 * x1;
#pragma unroll
    for (int m = 16; m > 0; m >>= 1) {
        s  += __shfl_xor_sync(0xffffffffu, s,  m);
        s2 += __shfl_xor_sync(0xffffffffu, s2, m);
    }
    float mean = s * (1.f / 64.f);
    float var  = s2 * (1.f / 64.f) - mean * mean;
    float inv  = rsqrtf(var + 1e-6f);
    p[lane]      = (x0 - mean) * inv * g[lane]      + b[lane];
    p[lane + 32] = (x1 - mean) * inv * g[lane + 32] + b[lane + 32];
}

// ---------------- attention (flash style), one 64-row Q tile per block --------
__global__ __launch_bounds__(256) void attn_kernel(
    const float* __restrict__ q, const float* __restrict__ k,
    const float* __restrict__ v, float* __restrict__ o)
{
    extern __shared__ float sm[];
    float* Qs = sm;                     // 64*64
    float* Ks = sm + 4096;              // 64 cols, stride 68 (transposed); reused as Ps
    float* Vs = sm + 4096 + 64 * 68;    // 64*64
    int qt = blockIdx.x, h = blockIdx.y, w = blockIdx.z;
    int tid = threadIdx.x;
    int r0 = (tid >> 4) * 4, c0 = (tid & 15) * 4;
    const size_t base = (size_t)w * LWIN * DIMC + (size_t)h * HD_;

#pragma unroll 4
    for (int i = 0; i < 16; i++) {
        int e = tid + i * 256; int r = e >> 6, d = e & 63;
        Qs[r * 64 + d] = q[base + (size_t)(qt * 64 + r) * DIMC + d] * 0.125f;
    }

    float m[4], l[4], accO[4][4];
#pragma unroll
    for (int i = 0; i < 4; i++) {
        m[i] = -1e30f; l[i] = 0.f;
#pragma unroll
        for (int j = 0; j < 4; j++) accO[i][j] = 0.f;
    }

    for (int kt = 0; kt < 20; kt++) {
        __syncthreads();
#pragma unroll 4
        for (int i = 0; i < 16; i++) {
            int e = tid + i * 256; int r = e >> 6, d = e & 63;
            size_t gi = base + (size_t)(kt * 64 + r) * DIMC + d;
            Ks[d * 68 + r] = k[gi];
            Vs[r * 64 + d] = v[gi];
        }
        __syncthreads();

        float s[4][4];
#pragma unroll
        for (int i = 0; i < 4; i++)
#pragma unroll
            for (int j = 0; j < 4; j++) s[i][j] = 0.f;

#pragma unroll 4
        for (int d = 0; d < 64; d++) {
            float4 kv = *(const float4*)(Ks + d * 68 + c0);
            float a0 = Qs[(r0 + 0) * 64 + d];
            float a1 = Qs[(r0 + 1) * 64 + d];
            float a2 = Qs[(r0 + 2) * 64 + d];
            float a3 = Qs[(r0 + 3) * 64 + d];
            s[0][0] += a0 * kv.x; s[0][1] += a0 * kv.y; s[0][2] += a0 * kv.z; s[0][3] += a0 * kv.w;
            s[1][0] += a1 * kv.x; s[1][1] += a1 * kv.y; s[1][2] += a1 * kv.z; s[1][3] += a1 * kv.w;
            s[2][0] += a2 * kv.x; s[2][1] += a2 * kv.y; s[2][2] += a2 * kv.z; s[2][3] += a2 * kv.w;
            s[3][0] += a3 * kv.x; s[3][1] += a3 * kv.y; s[3][2] += a3 * kv.z; s[3][3] += a3 * kv.w;
        }

        float p[4][4];
#pragma unroll
        for (int i = 0; i < 4; i++) {
            float tm = fmaxf(fmaxf(s[i][0], s[i][1]), fmaxf(s[i][2], s[i][3]));
#pragma unroll
            for (int msk = 8; msk > 0; msk >>= 1)
                tm = fmaxf(tm, __shfl_xor_sync(0xffffffffu, tm, msk));
            float mn = fmaxf(m[i], tm);
            float f  = expf(m[i] - mn);
            m[i] = mn;
            float rs = 0.f;
#pragma unroll
            for (int j = 0; j < 4; j++) { p[i][j] = expf(s[i][j] - mn); rs += p[i][j]; }
#pragma unroll
            for (int msk = 8; msk > 0; msk >>= 1)
                rs += __shfl_xor_sync(0xffffffffu, rs, msk);
            l[i] = l[i] * f + rs;
#pragma unroll
            for (int j = 0; j < 4; j++) accO[i][j] *= f;
        }

        __syncthreads();   // all Ks reads done before overwrite with P
#pragma unroll
        for (int i = 0; i < 4; i++) {
            float4 pv = make_float4(p[i][0], p[i][1], p[i][2], p[i][3]);
            *(float4*)(Ks + (r0 + i) * 68 + c0) = pv;
        }
        __syncthreads();

#pragma unroll 2
        for (int jj = 0; jj < 64; jj++) {
            float4 vv = *(const float4*)(Vs + jj * 64 + c0);
            float p0 = Ks[(r0 + 0) * 68 + jj];
            float p1 = Ks[(r0 + 1) * 68 + jj];
            float p2 = Ks[(r0 + 2) * 68 + jj];
            float p3 = Ks[(r0 + 3) * 68 + jj];
            accO[0][0] += p0 * vv.x; accO[0][1] += p0 * vv.y; accO[0][2] += p0 * vv.z; accO[0][3] += p0 * vv.w;
            accO[1][0] += p1 * vv.x; accO[1][1] += p1 * vv.y; accO[1][2] += p1 * vv.z; accO[1][3] += p1 * vv.w;
            accO[2][0] += p2 * vv.x; accO[2][1] += p2 * vv.y; accO[2][2] += p2 * vv.z; accO[2][3] += p2 * vv.w;
            accO[3][0] += p3 * vv.x; accO[3][1] += p3 * vv.y; accO[3][2] += p3 * vv.z; accO[3][3] += p3 * vv.w;
        }
    }

#pragma unroll
    for (int i = 0; i < 4; i++) {
        float invl = 1.f / l[i];
        float4 ov = make_float4(accO[i][0] * invl, accO[i][1] * invl,
                                accO[i][2] * invl, accO[i][3] * invl);
        *(float4*)(o + base + (size_t)(qt * 64 + r0 + i) * DIMC + c0) = ov;
    }
}

// ---------------- combine: hidden residual + pyramid-weighted window blend -----
__global__ __launch_bounds__(256) void combine_hidden_kernel(
    const float* __restrict__ hs, float* __restrict__ out)
{
    int gidx = blockIdx.x;               // 0..NTOK-1
    int tid  = threadIdx.x;
    int blk  = gidx / SROW;              // 0..5
    float acc[4] = {0.f, 0.f, 0.f, 0.f};
    float wsum = 0.f;
#pragma unroll
    for (int dw = -1; dw <= 0; dw++) {
        int w = blk + dw;
        if (w < 0 || w > 4) continue;
        int lv = gidx - w * SROW;        // in [0, LVV)
        float wt = c_pyr[lv / 144];
        wsum += wt;
        const float* op = g_o2 + ((size_t)w * LWIN + TENC + lv) * DIMC;
#pragma unroll
        for (int i = 0; i < 4; i++) acc[i] += wt * op[tid + i * 256];
    }
    float inv = 1.f / wsum;
#pragma unroll
    for (int i = 0; i < 4; i++) {
        int d = tid + i * 256;
        out[(size_t)gidx * DIMC + d] =
            hs[(size_t)gidx * DIMC + d] + g_emb1[2048 + d] * acc[i] * inv;
    }
}

// ---------------- combine: enc residual + mean over windows ----------------
__global__ __launch_bounds__(256) void combine_enc_kernel(
    const float* __restrict__ enc, float* __restrict__ out)
{
    int t = blockIdx.x; int tid = threadIdx.x;
#pragma unroll
    for (int i = 0; i < 4; i++) {
        int d = tid + i * 256;
        float a = 0.f;
#pragma unroll
        for (int w = 0; w < WQN; w++)
            a += g_o2[((size_t)w * LWIN + t) * DIMC + d];
        out[(size_t)t * DIMC + d] =
            enc[(size_t)t * DIMC + d] + g_emb1[5120 + d] * a * 0.2f;
    }
}

// ---------------- build ff_in = [mod-LN2(enc_new); mod-LN2(hidden_new)] --------
__global__ __launch_bounds__(256) void build_ffin_kernel(
    const float* __restrict__ dout,
    const float* __restrict__ g, const float* __restrict__ b)
{
    int row = blockIdx.x;                // 0..MFF-1
    const float* src; int sc_off, sh_off;
    if (row < TENC) { src = dout + (size_t)NTOK * DIMC + (size_t)row * DIMC; sc_off = 4096; sh_off = 3072; }
    else            { src = dout + (size_t)(row - TENC) * DIMC;              sc_off = 1024; sh_off = 0;    }
    int tid = threadIdx.x;
    float x[4]; float s = 0.f, s2 = 0.f;
#pragma unroll
    for (int i = 0; i < 4; i++) {
        x[i] = src[tid + i * 256];
        s += x[i]; s2 += x[i] * x[i];
    }
    block_reduce_2(s, s2);
    float mean = s * (1.f / DIMC);
    float var  = s2 * (1.f / DIMC) - mean * mean;
    float inv  = rsqrtf(var + 1e-5f);
    float* dst = g_ffin + (size_t)row * DIMC;
#pragma unroll
    for (int i = 0; i < 4; i++) {
        int d = tid + i * 256;
        float v = (x[i] - mean) * inv * g[d] + b[d];
        dst[d] = v * (1.f + g_emb2[sc_off + d]) + g_emb2[sh_off + d];
    }
}

// ---------------- final residual add --------------------------------------
__global__ __launch_bounds__(256) void final_add_kernel(float* __restrict__ dout)
{
    int row = blockIdx.x;                // 0..MFF-1
    int tid = threadIdx.x;
    if (row < TENC) {
        float* p = dout + (size_t)NTOK * DIMC + (size_t)row * DIMC;
#pragma unroll
        for (int i = 0; i < 4; i++) {
            int d = tid + i * 256;
            p[d] += g_emb2[5120 + d] * g_ffout[(size_t)row * DIMC + d];
        }
    } else {
        float* p = dout + (size_t)(row - TENC) * DIMC;
#pragma unroll
        for (int i = 0; i < 4; i++) {
            int d = tid + i * 256;
            p[d] += g_emb2[2048 + d] * g_ffout[(size_t)row * DIMC + d];
        }
    }
}

// ---------------- host side ----------------
static void launch_gemm(const float* A, const float* B, const float* bias,
                        float* C, int M, int N, int K, int act)
{
    dim3 grid(N / 128, M / 128);
    gemm_kernel<<<grid, 256>>>(A, B, bias, C, M, N, K, act);
}

extern "C" void kernel_launch(void* const* d_in, const int* in_sizes, int n_in,
                              void* d_out, int out_size)
{
    const float* hs    = (const float*)d_in[0];
    const float* enc   = (const float*)d_in[1];
    const float* temb  = (const float*)d_in[2];
    const float* n1w   = (const float*)d_in[3];
    const float* n1b   = (const float*)d_in[4];
    const float* n1g   = (const float*)d_in[5];
    const float* n1bb  = (const float*)d_in[6];
    const float* wq    = (const float*)d_in[7];
    const float* wk    = (const float*)d_in[8];
    const float* wv    = (const float*)d_in[9];
    const float* nqg   = (const float*)d_in[10];
    const float* nqb   = (const float*)d_in[11];
    const float* nkg   = (const float*)d_in[12];
    const float* nkb   = (const float*)d_in[13];
    const float* wo    = (const float*)d_in[14];
    const float* bo    = (const float*)d_in[15];
    const float* n2w   = (const float*)d_in[16];
    const float* n2b   = (const float*)d_in[17];
    const float* n2g   = (const float*)d_in[18];
    const float* n2bb  = (const float*)d_in[19];
    const float* ffw1  = (const float*)d_in[20];
    const float* ffb1  = (const float*)d_in[21];
    const float* ffw2  = (const float*)d_in[22];
    const float* ffb2  = (const float*)d_in[23];
    (void)in_sizes; (void)n_in;

    float* out = (float*)d_out;
    float* out_hidden = out;                           // [NTOK, DIMC]
    float* out_enc    = out + (size_t)NTOK * DIMC;     // [TENC, DIMC]
    (void)out_size;

    // resolve scratch symbol addresses (host cannot take &__device__ directly)
    float *p_x, *p_q, *p_k, *p_v, *p_ao, *p_o2, *p_ffin, *p_h1, *p_ffout;
    cudaGetSymbolAddress((void**)&p_x,    g_x);
    cudaGetSymbolAddress((void**)&p_q,    g_q);
    cudaGetSymbolAddress((void**)&p_k,    g_k);
    cudaGetSymbolAddress((void**)&p_v,    g_v);
    cudaGetSymbolAddress((void**)&p_ao,   g_ao);
    cudaGetSymbolAddress((void**)&p_o2,   g_o2);
    cudaGetSymbolAddress((void**)&p_ffin, g_ffin);
    cudaGetSymbolAddress((void**)&p_h1,   g_h1);
    cudaGetSymbolAddress((void**)&p_ffout,g_ffout);

    const int ATTN_SMEM = (4096 + 64 * 68 + 64 * 64) * 4;  // 50176 B
    cudaFuncSetAttribute(attn_kernel, cudaFuncAttributeMaxDynamicSharedMemorySize, ATTN_SMEM);

    // 1. modulation embeddings
    emb_kernel<<<48, 256>>>(temb, n1w, n1b, n2w, n2b);
    // 2. x = modulated LN of [enc ; gathered chunks]
    build_x_kernel<<<MQ, 256>>>(hs, enc, n1g, n1bb);
    // 3. qkv projections
    launch_gemm(p_x, wq, nullptr, p_q, MQ, DIMC, DIMC, 0);
    launch_gemm(p_x, wk, nullptr, p_k, MQ, DIMC, DIMC, 0);
    launch_gemm(p_x, wv, nullptr, p_v, MQ, DIMC, DIMC, 0);
    // 4. per-head LN on q, k
    qkln_kernel<<<MQ * HEADS_ / 8, 256>>>(p_q, nqg, nqb);
    qkln_kernel<<<MQ * HEADS_ / 8, 256>>>(p_k, nkg, nkb);
    // 5. attention
    attn_kernel<<<dim3(LWIN / 64, HEADS_, WQN), 256, ATTN_SMEM>>>(p_q, p_k, p_v, p_ao);
    // 6. output projection
    launch_gemm(p_ao, wo, bo, p_o2, MQ, DIMC, DIMC, 0);
    // 7. residual + window blending
    combine_hidden_kernel<<<NTOK, 256>>>(hs, out_hidden);
    combine_enc_kernel<<<TENC, 256>>>(enc, out_enc);
    // 8. FFN
    build_ffin_kernel<<<MFF, 256>>>(out, n2g, n2bb);
    launch_gemm(p_ffin, ffw1, ffb1, p_h1, MFF, 4096, DIMC, 1);
    launch_gemm(p_h1, ffw2, ffb2, p_ffout, MFF, DIMC, 4096, 0);
    // 9. final gated residual
    final_add_kernel<<<MFF, 256>>>(out);
}